// round 9
// baseline (speedup 1.0000x reference)
#include <cuda_runtime.h>
#include <cuda_fp16.h>

// ---------------------------------------------------------------------------
// LocalTransformerBlock, fp16 mma.sync (m16n8k16, fp32 accum) everywhere.
// R9: GEMM CTA tile 128x256 (warp tile 64x64, 8 warps), 3-stage cp.async
//     pipeline (wait_group 1). Attention/LN/prep identical to R8.
// B=4, L=4096, D=512, H=8, DH=64, MLP=2048, BS=128
// ---------------------------------------------------------------------------

#define NTOK 16384
#define D_   512
#define DH_  64
#define QKVN 1536
#define MLPD 2048
#define BS_  128

// ---- device scratch ----
__device__ __half g_xin[NTOK * D_];
__device__ __half g_qkv[NTOK * QKVN];
__device__ __half g_ctx[NTOK * D_];
__device__ float  g_x[NTOK * D_];
__device__ __half g_y[NTOK * D_];
__device__ __half g_h[NTOK * MLPD];
__device__ __half g_wqkv[QKVN * D_];   // [N][K] transposed
__device__ __half g_wot[D_ * D_];
__device__ __half g_w1t[MLPD * D_];
__device__ __half g_w2t[D_ * MLPD];

// ---- helpers ----
__device__ __forceinline__ float gelu_tanh(float x) {
    float a = 0.7978845608028654f * (x + 0.044715f * x * x * x);
    float t;
    asm("tanh.approx.f32 %0, %1;" : "=f"(t) : "f"(a));
    return 0.5f * x * (1.0f + t);
}
__device__ __forceinline__ void cp16(unsigned dst, const void* src) {
    asm volatile("cp.async.cg.shared.global [%0], [%1], 16;\n" :: "r"(dst), "l"(src));
}
#define CP_COMMIT asm volatile("cp.async.commit_group;\n")
#define CP_WAIT0  asm volatile("cp.async.wait_group 0;\n")
#define CP_WAIT1  asm volatile("cp.async.wait_group 1;\n")

#define LDSM4(r0, r1, r2, r3, addr)                                            \
    asm volatile("ldmatrix.sync.aligned.m8n8.x4.shared.b16 {%0,%1,%2,%3}, [%4];" \
        : "=r"(r0), "=r"(r1), "=r"(r2), "=r"(r3) : "r"(addr))

#define LDSM4T(r0, r1, r2, r3, addr)                                           \
    asm volatile("ldmatrix.sync.aligned.m8n8.x4.trans.shared.b16 {%0,%1,%2,%3}, [%4];" \
        : "=r"(r0), "=r"(r1), "=r"(r2), "=r"(r3) : "r"(addr))

// fp16 mma m16n8k16, fp32 accum
#define MMA16(c, a0, a1, a2, a3, b0, b1)                                       \
    asm volatile(                                                              \
        "mma.sync.aligned.m16n8k16.row.col.f32.f16.f16.f32 "                   \
        "{%0,%1,%2,%3},{%4,%5,%6,%7},{%8,%9},{%0,%1,%2,%3};"                   \
        : "+f"((c)[0]), "+f"((c)[1]), "+f"((c)[2]), "+f"((c)[3])               \
        : "r"(a0), "r"(a1), "r"(a2), "r"(a3), "r"(b0), "r"(b1))

// ---------------------------------------------------------------------------
// Unified weight prep: transpose + fp16 convert, one launch, 3072 tiles.
// ---------------------------------------------------------------------------
__global__ void __launch_bounds__(256)
prep_all(const float* __restrict__ wq, const float* __restrict__ wk,
         const float* __restrict__ wv, const float* __restrict__ wo,
         const float* __restrict__ w1, const float* __restrict__ w2,
         __half* __restrict__ dwqkv, __half* __restrict__ dwot,
         __half* __restrict__ dw1t, __half* __restrict__ dw2t) {
    __shared__ float t[32][33];
    const int b = blockIdx.x;
    const float* src; __half* dst; int R, C, n0, k0;
    if (b < 768) {
        const int wsel = b >> 8, r = b & 255;
        src = wsel == 0 ? wq : (wsel == 1 ? wk : wv);
        dst = dwqkv + (size_t)wsel * D_ * D_;
        R = D_; C = D_; n0 = (r & 15) * 32; k0 = (r >> 4) * 32;
    } else if (b < 1024) {
        const int r = b - 768;
        src = wo; dst = dwot;
        R = D_; C = D_; n0 = (r & 15) * 32; k0 = (r >> 4) * 32;
    } else if (b < 2048) {
        const int r = b - 1024;
        src = w1; dst = dw1t;
        R = D_; C = MLPD; n0 = (r & 63) * 32; k0 = (r >> 6) * 32;
    } else {
        const int r = b - 2048;
        src = w2; dst = dw2t;
        R = MLPD; C = D_; n0 = (r & 15) * 32; k0 = (r >> 4) * 32;
    }
    const int x = threadIdx.x, y = threadIdx.y;
#pragma unroll
    for (int i = 0; i < 32; i += 8)
        t[y + i][x] = src[(size_t)(k0 + y + i) * C + n0 + x];
    __syncthreads();
#pragma unroll
    for (int i = 0; i < 32; i += 8)
        dst[(size_t)(n0 + y + i) * R + k0 + x] = __float2half_rn(t[x][y + i]);
}

// ---------------------------------------------------------------------------
// LayerNorm: fp32 in -> fp16 out. One block per token row, 128 threads.
// ---------------------------------------------------------------------------
__global__ void __launch_bounds__(128)
ln_kernel(const float* __restrict__ in, const float* __restrict__ scale,
          const float* __restrict__ bias, __half* __restrict__ out) {
    const int row = blockIdx.x;
    const int tid = threadIdx.x;
    float4 v = reinterpret_cast<const float4*>(in + (size_t)row * D_)[tid];
    float s  = v.x + v.y + v.z + v.w;
    float s2 = v.x * v.x + v.y * v.y + v.z * v.z + v.w * v.w;
#pragma unroll
    for (int o = 16; o > 0; o >>= 1) {
        s  += __shfl_xor_sync(0xffffffffu, s, o);
        s2 += __shfl_xor_sync(0xffffffffu, s2, o);
    }
    __shared__ float rs[4], rq[4];
    if ((tid & 31) == 0) { rs[tid >> 5] = s; rq[tid >> 5] = s2; }
    __syncthreads();
    s  = rs[0] + rs[1] + rs[2] + rs[3];
    s2 = rq[0] + rq[1] + rq[2] + rq[3];
    const float mu  = s * (1.0f / D_);
    const float var = s2 * (1.0f / D_) - mu * mu;
    const float inv = rsqrtf(var + 1e-6f);
    float4 sc = reinterpret_cast<const float4*>(scale)[tid];
    float4 bi = reinterpret_cast<const float4*>(bias)[tid];
    __half2 h0 = __floats2half2_rn((v.x - mu) * inv * sc.x + bi.x,
                                   (v.y - mu) * inv * sc.y + bi.y);
    __half2 h1 = __floats2half2_rn((v.z - mu) * inv * sc.z + bi.z,
                                   (v.w - mu) * inv * sc.w + bi.w);
    __half2* op = reinterpret_cast<__half2*>(out + (size_t)row * D_) + tid * 2;
    op[0] = h0; op[1] = h1;
}

// ---------------------------------------------------------------------------
// fp16 GEMM: C[M,N] = A[M,K] * Bt[N,K], fp32 accum.
// BM=128, BN=256, BK=64, 256 threads (8 warps 2x4, warp tile 64x64),
// 3-stage cp.async pipeline, XOR-swizzled smem, ldmatrix.
// ---------------------------------------------------------------------------
constexpr int EPI_H = 0;        // C fp16 = acc                    (qkv)
constexpr int EPI_ADD_F = 1;    // C fp32 = acc + add              (o-proj)
constexpr int EPI_GELU_H = 2;   // C fp16 = gelu(acc + bias)       (mlp1)
constexpr int EPI_ADDBIAS_F = 3;// C fp32 = acc + bias + add       (mlp2)

constexpr int ASTB = 128 * 64 * 2;           // 16 KB A stage
constexpr int STB  = ASTB + 256 * 64 * 2;    // + 32 KB B = 48 KB/stage
constexpr int GM_DSMEM = 3 * STB + 1024;     // 3 stages

template <int EPI>
__global__ void __launch_bounds__(256, 1)
gemm_h(const __half* __restrict__ A, const __half* __restrict__ Bt,
       void* __restrict__ Cv, int M, int N, int K,
       const float* __restrict__ bias, const float* __restrict__ add) {
    extern __shared__ float dyn[];
    char* smf = (char*)(((size_t)(char*)dyn + 1023) & ~(size_t)1023);
    const unsigned sbase = (unsigned)__cvta_generic_to_shared(smf);

    const int tid = threadIdx.x, lane = tid & 31, w = tid >> 5;
    const int g = lane >> 2, q = lane & 3;
    const int wm = (w >> 2) * 64, wn = (w & 3) * 64;
    const int bm = blockIdx.y * 128, bn = blockIdx.x * 256;
    const int KT = K >> 6;

    const int a_row = lane & 15;
    const int a_hi  = lane >> 4;
    const int b_row = (lane & 7) + ((lane >> 4) << 3);
    const int b_hi  = (lane >> 3) & 1;

    float acc[4][8][4];
#pragma unroll
    for (int mt = 0; mt < 4; mt++)
#pragma unroll
        for (int nt = 0; nt < 8; nt++)
#pragma unroll
            for (int l = 0; l < 4; l++) acc[mt][nt][l] = 0.0f;

    auto load_stage = [&](int s, int kt) {
        const unsigned ua = sbase + s * STB;
        const unsigned ub = ua + ASTB;
        const __half* Ag = A + (size_t)bm * K + kt * 64;
        const __half* Bg = Bt + (size_t)bn * K + kt * 64;
#pragma unroll
        for (int t = 0; t < 4; t++) {               // A: 128 rows x 128B
            const int idx = tid + t * 256;
            const int r = idx >> 3, c = idx & 7;
            cp16(ua + r * 128 + ((c ^ (r & 7)) << 4), Ag + (size_t)r * K + c * 8);
        }
#pragma unroll
        for (int t = 0; t < 8; t++) {               // B: 256 rows x 128B
            const int idx = tid + t * 256;
            const int r = idx >> 3, c = idx & 7;
            cp16(ub + r * 128 + ((c ^ (r & 7)) << 4), Bg + (size_t)r * K + c * 8);
        }
        CP_COMMIT;
    };

    load_stage(0, 0);
    if (KT > 1) load_stage(1, 1);

    int st = 0;
    for (int kt = 0; kt < KT; kt++) {
        if (kt + 1 < KT) { CP_WAIT1; } else { CP_WAIT0; }
        __syncthreads();
        if (kt + 2 < KT) {
            int ns = st + 2; if (ns >= 3) ns -= 3;
            load_stage(ns, kt + 2);
        }

        const unsigned uA = sbase + st * STB;
        const unsigned uB = uA + ASTB;
#pragma unroll
        for (int ks = 0; ks < 4; ks++) {
            const int ch0 = 2 * ks;
            unsigned af[4][4];
#pragma unroll
            for (int mt = 0; mt < 4; mt++) {
                const int r = wm + mt * 16 + a_row;
                LDSM4(af[mt][0], af[mt][1], af[mt][2], af[mt][3],
                      uA + r * 128 + (((ch0 + a_hi) ^ (r & 7)) << 4));
            }
#pragma unroll
            for (int bt = 0; bt < 4; bt++) {
                const int nr = wn + bt * 16 + b_row;
                unsigned b0, b1, b2, b3;
                LDSM4(b0, b1, b2, b3,
                      uB + nr * 128 + (((ch0 + b_hi) ^ (nr & 7)) << 4));
#pragma unroll
                for (int mt = 0; mt < 4; mt++) {
                    MMA16(acc[mt][bt * 2 + 0], af[mt][0], af[mt][1],
                          af[mt][2], af[mt][3], b0, b1);
                    MMA16(acc[mt][bt * 2 + 1], af[mt][0], af[mt][1],
                          af[mt][2], af[mt][3], b2, b3);
                }
            }
        }
        if (++st == 3) st = 0;
    }

    // ---- epilogue ----
#pragma unroll
    for (int mt = 0; mt < 4; mt++) {
#pragma unroll
        for (int nt = 0; nt < 8; nt++) {
            const int r0 = bm + wm + mt * 16 + g;
            const int c0 = bn + wn + nt * 8 + 2 * q;
            float bx = 0.0f, by = 0.0f;
            if (EPI == EPI_GELU_H || EPI == EPI_ADDBIAS_F) {
                float2 bv = *reinterpret_cast<const float2*>(bias + c0);
                bx = bv.x; by = bv.y;
            }
#pragma unroll
            for (int hf = 0; hf < 2; hf++) {
                const int r = r0 + hf * 8;
                float v0 = acc[mt][nt][hf * 2 + 0] + bx;
                float v1 = acc[mt][nt][hf * 2 + 1] + by;
                const size_t idx = (size_t)r * N + c0;
                if (EPI == EPI_GELU_H) { v0 = gelu_tanh(v0); v1 = gelu_tanh(v1); }
                if (EPI == EPI_ADD_F || EPI == EPI_ADDBIAS_F) {
                    float2 av = *reinterpret_cast<const float2*>(add + idx);
                    v0 += av.x; v1 += av.y;
                    float2 o; o.x = v0; o.y = v1;
                    *reinterpret_cast<float2*>((float*)Cv + idx) = o;
                } else {
                    *reinterpret_cast<__half2*>((__half*)Cv + idx) =
                        __floats2half2_rn(v0, v1);
                }
            }
        }
    }
}

// ---------------------------------------------------------------------------
// Block-local attention, fp16 mma + ldmatrix (identical to R8).
// ---------------------------------------------------------------------------
constexpr int ATT_SMEM_BYTES = 49152 + 1024;

__global__ void __launch_bounds__(256)
attn_kernel(const __half* __restrict__ QKV, __half* __restrict__ CTX) {
    extern __shared__ char smem_raw[];
    char* smp = (char*)(((size_t)smem_raw + 1023) & ~(size_t)1023);
    const unsigned sb = (unsigned)__cvta_generic_to_shared(smp);
    const unsigned uQ = sb, uK = sb + 16384, uV = sb + 32768, uP = sb;

    const int tid = threadIdx.x, lane = tid & 31, w = tid >> 5;
    const int g = lane >> 2, q = lane & 3;
    const int blk = blockIdx.x >> 3;
    const int h   = blockIdx.x & 7;
    const int t0  = blk * BS_;
    const int fb  = h * DH_;

#pragma unroll
    for (int t = 0; t < 4; t++) {
        const int idx = tid + t * 256;
        const int r = idx >> 3, c = idx & 7;
        const __half* gl = QKV + (size_t)(t0 + r) * QKVN + fb + c * 8;
        const unsigned off = r * 128 + ((c ^ (r & 7)) << 4);
        cp16(uQ + off, gl);
        cp16(uK + off, gl + 512);
        cp16(uV + off, gl + 1024);
    }
    CP_COMMIT;
    CP_WAIT0;
    __syncthreads();

    const int mrow = w * 16;
    const int a_row = lane & 15, a_hi = lane >> 4;
    const int b_row = (lane & 7) + ((lane >> 4) << 3), b_hi = (lane >> 3) & 1;

    float sacc[16][4];
#pragma unroll
    for (int nt = 0; nt < 16; nt++)
#pragma unroll
        for (int l = 0; l < 4; l++) sacc[nt][l] = 0.0f;

#pragma unroll
    for (int ks = 0; ks < 4; ks++) {
        const int ch0 = 2 * ks;
        unsigned a0, a1, a2, a3;
        {
            const int r = mrow + a_row;
            LDSM4(a0, a1, a2, a3, uQ + r * 128 + (((ch0 + a_hi) ^ (r & 7)) << 4));
        }
#pragma unroll
        for (int bt = 0; bt < 8; bt++) {
            const int nr = bt * 16 + b_row;
            unsigned b0, b1, b2, b3;
            LDSM4(b0, b1, b2, b3, uK + nr * 128 + (((ch0 + b_hi) ^ (nr & 7)) << 4));
            MMA16(sacc[bt * 2 + 0], a0, a1, a2, a3, b0, b1);
            MMA16(sacc[bt * 2 + 1], a0, a1, a2, a3, b2, b3);
        }
    }
    __syncthreads();

    float m0 = -1e30f, m1 = -1e30f;
#pragma unroll
    for (int nt = 0; nt < 16; nt++) {
        sacc[nt][0] *= 0.125f; sacc[nt][1] *= 0.125f;
        sacc[nt][2] *= 0.125f; sacc[nt][3] *= 0.125f;
        m0 = fmaxf(m0, fmaxf(sacc[nt][0], sacc[nt][1]));
        m1 = fmaxf(m1, fmaxf(sacc[nt][2], sacc[nt][3]));
    }
    m0 = fmaxf(m0, __shfl_xor_sync(0xffffffffu, m0, 1));
    m0 = fmaxf(m0, __shfl_xor_sync(0xffffffffu, m0, 2));
    m1 = fmaxf(m1, __shfl_xor_sync(0xffffffffu, m1, 1));
    m1 = fmaxf(m1, __shfl_xor_sync(0xffffffffu, m1, 2));
    float s0 = 0.0f, s1 = 0.0f;
#pragma unroll
    for (int nt = 0; nt < 16; nt++) {
        sacc[nt][0] = expf(sacc[nt][0] - m0); s0 += sacc[nt][0];
        sacc[nt][1] = expf(sacc[nt][1] - m0); s0 += sacc[nt][1];
        sacc[nt][2] = expf(sacc[nt][2] - m1); s1 += sacc[nt][2];
        sacc[nt][3] = expf(sacc[nt][3] - m1); s1 += sacc[nt][3];
    }
    s0 += __shfl_xor_sync(0xffffffffu, s0, 1);
    s0 += __shfl_xor_sync(0xffffffffu, s0, 2);
    s1 += __shfl_xor_sync(0xffffffffu, s1, 1);
    s1 += __shfl_xor_sync(0xffffffffu, s1, 2);
    const float i0 = 1.0f / s0, i1 = 1.0f / s1;

    {
        char* pp = smp;
#pragma unroll
        for (int nt = 0; nt < 16; nt++) {
            const int r0 = mrow + g, r1 = mrow + g + 8;
            const unsigned o0 = r0 * 256 + ((nt ^ (r0 & 7)) << 4) + 4 * q;
            const unsigned o1 = r1 * 256 + ((nt ^ (r1 & 7)) << 4) + 4 * q;
            *reinterpret_cast<__half2*>(pp + o0) =
                __floats2half2_rn(sacc[nt][0] * i0, sacc[nt][1] * i0);
            *reinterpret_cast<__half2*>(pp + o1) =
                __floats2half2_rn(sacc[nt][2] * i1, sacc[nt][3] * i1);
        }
    }
    __syncwarp();

    float o[8][4];
#pragma unroll
    for (int nt = 0; nt < 8; nt++)
#pragma unroll
        for (int l = 0; l < 4; l++) o[nt][l] = 0.0f;

    const int vi  = lane >> 3;
    const int vrk = ((vi & 1) << 3) + (lane & 7);
    const int vch = vi >> 1;
#pragma unroll
    for (int ks = 0; ks < 8; ks++) {
        unsigned a0, a1, a2, a3;
        {
            const int r = mrow + a_row;
            LDSM4(a0, a1, a2, a3,
                  uP + r * 256 + (((2 * ks + a_hi) ^ (r & 7)) << 4));
        }
#pragma unroll
        for (int vt = 0; vt < 4; vt++) {
            const int rk = ks * 16 + vrk;
            const int ch = vt * 2 + vch;
            unsigned b0, b1, b2, b3;
            LDSM4T(b0, b1, b2, b3, uV + rk * 128 + ((ch ^ (rk & 7)) << 4));
            MMA16(o[vt * 2 + 0], a0, a1, a2, a3, b0, b1);
            MMA16(o[vt * 2 + 1], a0, a1, a2, a3, b2, b3);
        }
    }

#pragma unroll
    for (int nt = 0; nt < 8; nt++) {
        const int d0 = nt * 8 + 2 * q;
        const int r = t0 + mrow + g;
        *reinterpret_cast<__half2*>(CTX + (size_t)r * D_ + fb + d0) =
            __floats2half2_rn(o[nt][0], o[nt][1]);
        *reinterpret_cast<__half2*>(CTX + (size_t)(r + 8) * D_ + fb + d0) =
            __floats2half2_rn(o[nt][2], o[nt][3]);
    }
}

// ---------------------------------------------------------------------------
// launch
// ---------------------------------------------------------------------------
extern "C" void kernel_launch(void* const* d_in, const int* in_sizes, int n_in,
                              void* d_out, int out_size) {
    const float* inputs = (const float*)d_in[0];
    const float* ln1s   = (const float*)d_in[1];
    const float* ln1b   = (const float*)d_in[2];
    const float* wq     = (const float*)d_in[3];
    const float* wk     = (const float*)d_in[4];
    const float* wv     = (const float*)d_in[5];
    const float* wo     = (const float*)d_in[6];
    const float* ln2s   = (const float*)d_in[7];
    const float* ln2b   = (const float*)d_in[8];
    const float* w1     = (const float*)d_in[9];
    const float* b1     = (const float*)d_in[10];
    const float* w2     = (const float*)d_in[11];
    const float* b2     = (const float*)d_in[12];
    float* out = (float*)d_out;

    void *p_xin, *p_qkv, *p_ctx, *p_x, *p_y, *p_h;
    void *p_wqkv, *p_wot, *p_w1t, *p_w2t;
    cudaGetSymbolAddress(&p_xin, g_xin);
    cudaGetSymbolAddress(&p_qkv, g_qkv);
    cudaGetSymbolAddress(&p_ctx, g_ctx);
    cudaGetSymbolAddress(&p_x, g_x);
    cudaGetSymbolAddress(&p_y, g_y);
    cudaGetSymbolAddress(&p_h, g_h);
    cudaGetSymbolAddress(&p_wqkv, g_wqkv);
    cudaGetSymbolAddress(&p_wot, g_wot);
    cudaGetSymbolAddress(&p_w1t, g_w1t);
    cudaGetSymbolAddress(&p_w2t, g_w2t);

    cudaFuncSetAttribute(gemm_h<EPI_H>,
        cudaFuncAttributeMaxDynamicSharedMemorySize, GM_DSMEM);
    cudaFuncSetAttribute(gemm_h<EPI_ADD_F>,
        cudaFuncAttributeMaxDynamicSharedMemorySize, GM_DSMEM);
    cudaFuncSetAttribute(gemm_h<EPI_GELU_H>,
        cudaFuncAttributeMaxDynamicSharedMemorySize, GM_DSMEM);
    cudaFuncSetAttribute(gemm_h<EPI_ADDBIAS_F>,
        cudaFuncAttributeMaxDynamicSharedMemorySize, GM_DSMEM);
    cudaFuncSetAttribute(attn_kernel,
        cudaFuncAttributeMaxDynamicSharedMemorySize, ATT_SMEM_BYTES);

    // launch 0: unified weight prep
    prep_all<<<3072, dim3(32, 8)>>>(wq, wk, wv, wo, w1, w2,
        (__half*)p_wqkv, (__half*)p_wot, (__half*)p_w1t, (__half*)p_w2t);

    // launch 1: LN1
    ln_kernel<<<NTOK, 128>>>(inputs, ln1s, ln1b, (__half*)p_xin);

    // launch 2: fused QKV GEMM [16384,512] x [1536,512]^T
    gemm_h<EPI_H><<<dim3(6, 128), 256, GM_DSMEM>>>(
        (__half*)p_xin, (__half*)p_wqkv, p_qkv,
        NTOK, QKVN, D_, nullptr, nullptr);

    // launch 3: attention
    attn_kernel<<<1024, 256, ATT_SMEM_BYTES>>>((__half*)p_qkv, (__half*)p_ctx);

    // launch 4: O projection + residual -> x (fp32)
    gemm_h<EPI_ADD_F><<<dim3(2, 128), 256, GM_DSMEM>>>(
        (__half*)p_ctx, (__half*)p_wot, p_x,
        NTOK, D_, D_, nullptr, inputs);

    // launch 5: LN2
    ln_kernel<<<NTOK, 128>>>((float*)p_x, ln2s, ln2b, (__half*)p_y);

    // launch 6: MLP1 (bias + gelu -> fp16)
    gemm_h<EPI_GELU_H><<<dim3(8, 128), 256, GM_DSMEM>>>(
        (__half*)p_y, (__half*)p_w1t, p_h,
        NTOK, MLPD, D_, b1, nullptr);

    // launch 7: MLP2 (+bias +residual -> fp32 out)
    gemm_h<EPI_ADDBIAS_F><<<dim3(2, 128), 256, GM_DSMEM>>>(
        (__half*)p_h, (__half*)p_w2t, out,
        NTOK, D_, MLPD, b2, (float*)p_x);
}